// round 2
// baseline (speedup 1.0000x reference)
#include <cuda_runtime.h>
#include <math.h>

#define MDL   4
#define CDIM  1000
#define NV4   250          // CDIM/4 float4 per row
#define NTHR  128          // 4 warps: warp m handles model m

// Device globals (no allocation allowed).
__device__ double g_acc[2];
__device__ int    g_is64;

__global__ void cmcl_prologue(const int* __restrict__ t32) {
    g_acc[0] = 0.0;
    g_acc[1] = 0.0;
    // Detect int64 vs int32 targets: true int64 (values < 1000, little-endian)
    // has zero in every odd 32-bit word. int32 data matching that across 16
    // entries is essentially impossible (p ~ 1e-48).
    int is64 = 1;
    #pragma unroll
    for (int k = 0; k < 16; k++) {
        if (t32[2 * k + 1] != 0) { is64 = 0; break; }
    }
    g_is64 = is64;
}

__global__ __launch_bounds__(NTHR) void cmcl_main(
    const float* __restrict__ logits,        // (M, B, C) fp32
    const int*   __restrict__ t32,           // targets, int32 view
    float* __restrict__ oracle,              // (B, C) or null
    float* __restrict__ idx_out,             // (B,)  or null
    int B)
{
    const int b    = blockIdx.x;
    const int warp = threadIdx.x >> 5;       // model index m
    const int lane = threadIdx.x & 31;

    __shared__ float s_ce[MDL];
    __shared__ float s_ent[MDL];
    __shared__ int   s_win;

    const int tgt = g_is64 ? t32[2 * b] : t32[b];

    // Row of model `warp`, sample `b`: 1000 contiguous floats, 16B-aligned.
    const float4* __restrict__ row =
        (const float4*)(logits + ((size_t)warp * (size_t)B + (size_t)b) * CDIM);

    // ---- single global read: buffer this lane's elements in registers ----
    float4 buf[8];
    #pragma unroll
    for (int k = 0; k < 8; k++) {
        int i = lane + 32 * k;
        if (i < NV4) buf[k] = __ldg(row + i);
    }

    // ---- pass 1: per-lane max ----
    float mx = -INFINITY;
    #pragma unroll
    for (int k = 0; k < 8; k++) {
        int i = lane + 32 * k;
        if (i < NV4) {
            mx = fmaxf(mx, fmaxf(fmaxf(buf[k].x, buf[k].y),
                                 fmaxf(buf[k].z, buf[k].w)));
        }
    }
    // warp max
    #pragma unroll
    for (int off = 16; off > 0; off >>= 1)
        mx = fmaxf(mx, __shfl_xor_sync(0xFFFFFFFFu, mx, off));

    // ---- pass 2: sum exp(x - mx), plain sum, target logit ----
    float sexp = 0.0f, ssum = 0.0f, tval = 0.0f;
    #pragma unroll
    for (int k = 0; k < 8; k++) {
        int i = lane + 32 * k;
        if (i < NV4) {
            float v[4] = {buf[k].x, buf[k].y, buf[k].z, buf[k].w};
            #pragma unroll
            for (int j = 0; j < 4; j++) {
                float x = v[j];
                ssum += x;
                sexp += expf(x - mx);                 // accurate exp
                if (4 * i + j == tgt) tval = x;
            }
        }
    }
    #pragma unroll
    for (int off = 16; off > 0; off >>= 1) {
        sexp += __shfl_xor_sync(0xFFFFFFFFu, sexp, off);
        ssum += __shfl_xor_sync(0xFFFFFFFFu, ssum, off);
        tval += __shfl_xor_sync(0xFFFFFFFFu, tval, off);
    }

    if (lane == 0) {
        float lse = mx + logf(sexp);
        // jax: ce = -(x_t - lse); ent = lse - mean(x) - log(C)
        s_ce[warp]  = lse - tval;
        s_ent[warp] = lse - ssum * (1.0f / CDIM) - logf((float)CDIM);
    }
    __syncthreads();

    if (threadIdx.x == 0) {
        // argmin_m (ce + total_ent - ent); total_ent is constant in m so the
        // winner is argmin (ce - ent). Strict <: first-min wins (jax tie-break).
        float best = s_ce[0] - s_ent[0];
        int   win  = 0;
        float entsum = s_ent[0];
        #pragma unroll
        for (int m = 1; m < MDL; m++) {
            entsum += s_ent[m];
            float sc = s_ce[m] - s_ent[m];
            if (sc < best) { best = sc; win = m; }
        }
        s_win = win;
        if (idx_out) idx_out[b] = (float)win;
        atomicAdd(&g_acc[0], (double)(s_ce[win] - s_ent[win]));
        atomicAdd(&g_acc[1], (double)entsum);
    }
    __syncthreads();

    // ---- oracle row copy (source is L1/L2-hot: this block just read it) ----
    if (oracle) {
        const float* __restrict__ src =
            logits + ((size_t)s_win * (size_t)B + (size_t)b) * CDIM;
        float* __restrict__ dst = oracle + (size_t)b * CDIM;  // may be 4B-aligned only
        for (int i = threadIdx.x; i < CDIM; i += NTHR)
            dst[i] = __ldg(src + i);
    }
}

__global__ void cmcl_finalize(float* loss, int B) {
    if (loss) loss[0] = (float)((g_acc[0] + g_acc[1]) / (double)B);
}

extern "C" void kernel_launch(void* const* d_in, const int* in_sizes, int n_in,
                              void* d_out, int out_size)
{
    const float* logits = (const float*)d_in[0];
    const int*   t32    = (const int*)d_in[1];
    const int B = in_sizes[1];                 // 8192

    float* out = (float*)d_out;
    const long long bc = (long long)B * CDIM;

    // Output layout: tuple (new_loss, oracle_logits, min_index) flattened.
    float* loss_p   = nullptr;
    float* oracle_p = nullptr;
    float* idx_p    = nullptr;
    long long osz = (long long)out_size;
    if (osz >= 1 + bc + B) {                   // full tuple
        loss_p   = out;
        oracle_p = out + 1;
        idx_p    = out + 1 + bc;
    } else if (osz == bc + B) {                // (oracle, idx)
        oracle_p = out;
        idx_p    = out + bc;
    } else if (osz == bc) {                    // oracle only
        oracle_p = out;
    } else if (osz == B) {                     // idx only
        idx_p = out;
    } else {                                   // scalar loss only
        loss_p = out;
    }

    cmcl_prologue<<<1, 1>>>(t32);
    cmcl_main<<<B, NTHR>>>(logits, t32, oracle_p, idx_p, B);
    cmcl_finalize<<<1, 1>>>(loss_p, B);
}